// round 15
// baseline (speedup 1.0000x reference)
#include <cuda_runtime.h>
#include <cuda_fp16.h>
#include <cstdint>
#include <math.h>

#define D_MODEL 2048
#define N_EXP   64
#define TOP_K   8
#define SCALE   0.022097086912079608f
#define EPS     4.2e-5f
#define MAX_T   16384
#define CTA_TOK 64
#define NCHUNK  32            // 2048 / 64
#define WPITCH  144           // bytes per 64-half W smem row (ldmatrix-friendly)
#define TPITCH  528           // bytes per 16x16 A-fragment tile (bank-rotated)
#define LROW    66

// ---- device globals (no allocations allowed; zero-initialized at load) -----
__device__ int   g_flag_count;   // 0 at call 1; reset by combine ticket after
__device__ int   g_done_count;
__device__ int   g_flags[MAX_T];
// panel partials: [batch(<=512)][tok 32][panel 4][exp 64]
__device__ float g_partial[(MAX_T / 32) * 32 * 4 * 64];

// ---- fp16 MMA ---------------------------------------------------------------
static __device__ __forceinline__ void mma16816(float* d, const uint32_t* a,
                                                uint32_t b0, uint32_t b1) {
    asm volatile(
        "mma.sync.aligned.m16n8k16.row.col.f32.f16.f16.f32 "
        "{%0,%1,%2,%3}, {%4,%5,%6,%7}, {%8,%9}, {%0,%1,%2,%3};"
        : "+f"(d[0]), "+f"(d[1]), "+f"(d[2]), "+f"(d[3])
        : "r"(a[0]), "r"(a[1]), "r"(a[2]), "r"(a[3]), "r"(b0), "r"(b1));
}

static __device__ __forceinline__ void ldmatrix_x4(
    uint32_t& r0, uint32_t& r1, uint32_t& r2, uint32_t& r3, uint32_t saddr) {
    asm volatile(
        "ldmatrix.sync.aligned.m8n8.x4.shared.b16 {%0,%1,%2,%3}, [%4];"
        : "=r"(r0), "=r"(r1), "=r"(r2), "=r"(r3) : "r"(saddr));
}

static __device__ __forceinline__ uint32_t cvt2(float a, float b) {
    __half2 h = __floats2half2_rn(a, b);
    return *reinterpret_cast<uint32_t*>(&h);
}

// ---------------------------------------------------------------------------
// Main: x(fp16) x W(fp16, converted in-kernel) HMMA. A tile staged
// fragment-permuted (one LDS.128 per A frag); W staged PLAIN k-consecutive
// (pitch 144) and B frags loaded via ldmatrix.x4 (8 matrices = 2 instr per
// warp-ks). Fused top-9 / flag / softmax. CTA = 256 thr / 8 warps.
// ---------------------------------------------------------------------------
#define SM_A(s)  ((s) * (16 * TPITCH))                 // 2 x 8448 = 16896
#define SM_W(s)  (16896 + (s) * (64 * WPITCH))         // 2 x 9216 = 18432
#define SM_BIAS  35328
#define SM_TOT   35584

__global__ void __launch_bounds__(256, 2)
router_mma_kernel(const float* __restrict__ x, const float* __restrict__ W,
                  const float* __restrict__ bias, float* __restrict__ out, int T)
{
    __shared__ __align__(16) char sm[SM_TOT];

    const int tid  = threadIdx.x;
    const int wid  = tid >> 5;
    const int lane = tid & 31;
    const int tg   = wid >> 1;
    const int eh   = wid & 1;
    const int tokBase = blockIdx.x * CTA_TOK;
    const int wtok = tokBase + tg * 16;

    float* bias_sm = reinterpret_cast<float*>(sm + SM_BIAS);
    if (tid < N_EXP) bias_sm[tid] = bias[tid];

    const int n4 = lane >> 2;
    const int q4 = lane & 3;
    const int cp2 = q4 << 1;

    // ---- A writer mapping (proven): 4 float4 per thread, coalesced ---------
    int arow[4], adst0[4], adst1[4];
#pragma unroll
    for (int j = 0; j < 4; j++) {
        int u  = tid + 256 * j;
        int r  = u >> 4;
        int k0 = (u & 15) * 4;
        int tgw = r >> 4, rr = r & 15, rA = rr & 7, hifl = rr >> 3;
        int ks = k0 >> 4, kk = k0 & 15, khi = kk >> 3, qa = (kk & 7) >> 1;
        arow[j]  = r;
        int tbase = (tgw * 4 + ks) * TPITCH + (hifl + khi * 2) * 4;
        adst0[j] = tbase + (rA * 4 + qa) * 16;
        adst1[j] = tbase + (rA * 4 + qa + 1) * 16;
    }
    const int ak0_0 = (tid & 15) * 4;

    // ---- W mapping: expert e = tid>>2, 16-elem k-segment s = tid&3 ----------
    const float* wgp = W + (size_t)(tid >> 2) * D_MODEL + (tid & 3) * 16;
    const int    wse = (tid >> 2) * WPITCH + (tid & 3) * 32;   // bytes

    // ldmatrix lane address component: matrix id m = lane>>3
    //   e_off = ((lane>>4)&1)*8 + (lane&7), k_byte = ((lane>>3)&1)*16
    const uint32_t lm_lane_off =
        (uint32_t)((((lane >> 4) & 1) * 8 + (lane & 7)) * WPITCH +
                   ((lane >> 3) & 1) * 16);

    auto loadA = [&](int c, float4* av) {
#pragma unroll
        for (int j = 0; j < 4; j++)
            av[j] = *reinterpret_cast<const float4*>(
                x + (size_t)(tokBase + arow[j]) * D_MODEL + c * 64 + ak0_0);
    };
    auto storeA = [&](int s, const float4* av) {
#pragma unroll
        for (int j = 0; j < 4; j++) {
            *reinterpret_cast<uint32_t*>(sm + SM_A(s) + adst0[j]) =
                cvt2(av[j].x, av[j].y);
            *reinterpret_cast<uint32_t*>(sm + SM_A(s) + adst1[j]) =
                cvt2(av[j].z, av[j].w);
        }
    };
    auto loadW = [&](int c, float4* wv) {
#pragma unroll
        for (int j = 0; j < 4; j++)
            wv[j] = *reinterpret_cast<const float4*>(wgp + c * 64 + j * 4);
    };
    // convert + store plain k-consecutive (16 halves -> 32B)
    auto storeW = [&](int s, const float4* wv) {
        uint4 o0, o1;
        o0.x = cvt2(wv[0].x, wv[0].y); o0.y = cvt2(wv[0].z, wv[0].w);
        o0.z = cvt2(wv[1].x, wv[1].y); o0.w = cvt2(wv[1].z, wv[1].w);
        o1.x = cvt2(wv[2].x, wv[2].y); o1.y = cvt2(wv[2].z, wv[2].w);
        o1.z = cvt2(wv[3].x, wv[3].y); o1.w = cvt2(wv[3].z, wv[3].w);
        *reinterpret_cast<uint4*>(&sm[SM_W(s) + wse])      = o0;
        *reinterpret_cast<uint4*>(&sm[SM_W(s) + wse + 16]) = o1;
    };

    // prologue: stage chunk 0
    float4 av[4], wv[4];
    loadA(0, av);
    loadW(0, wv);
    storeA(0, av);
    storeW(0, wv);
    __syncthreads();

    float dh[4][4];
#pragma unroll
    for (int j = 0; j < 4; j++)
#pragma unroll
        for (int q = 0; q < 4; q++) dh[j][q] = 0.0f;

    for (int c = 0; c < NCHUNK; c++) {
        const int buf = c & 1;

        if (c + 1 < NCHUNK) {
            loadA(c + 1, av);
            loadW(c + 1, wv);
        }

        const char* AS = sm + SM_A(buf);
        const uint32_t WSH =
            (uint32_t)__cvta_generic_to_shared(sm + SM_W(buf)) +
            (uint32_t)(eh * 32 * WPITCH) + lm_lane_off;
#pragma unroll
        for (int ks = 0; ks < 4; ks++) {
            uint4 af = *reinterpret_cast<const uint4*>(
                AS + (tg * 4 + ks) * TPITCH + lane * 16);
            uint32_t a[4] = {af.x, af.y, af.z, af.w};
            // two ldmatrix.x4: expert octets {0,1} then {2,3} of this half
            uint32_t b0, b1, b2, b3;
            ldmatrix_x4(b0, b1, b2, b3, WSH + ks * 32);
            mma16816(dh[0], a, b0, b1);
            mma16816(dh[1], a, b2, b3);
            ldmatrix_x4(b0, b1, b2, b3, WSH + 16 * WPITCH + ks * 32);
            mma16816(dh[2], a, b0, b1);
            mma16816(dh[3], a, b2, b3);
        }
        if (c + 1 < NCHUNK) {
            storeA(buf ^ 1, av);
            storeW(buf ^ 1, wv);
        }
        __syncthreads();
    }

    // ---- epilogue: spill logits into W region, per-lane top-9 --------------
    float* lw = reinterpret_cast<float*>(sm + SM_W(0)) + tg * 16 * LROW;
#pragma unroll
    for (int j = 0; j < 4; j++) {
        int col = eh * 32 + j * 8 + cp2;
        lw[n4 * LROW + col]           = dh[j][0];
        lw[n4 * LROW + col + 1]       = dh[j][1];
        lw[(n4 + 8) * LROW + col]     = dh[j][2];
        lw[(n4 + 8) * LROW + col + 1] = dh[j][3];
    }
    __syncthreads();

    if (eh == 0 && lane < 16) {
        const int tok = wtok + lane;
        const float* row = lw + lane * LROW;
        const float NEG = -3.0e38f;

        float val[9]; int idx[9];
#pragma unroll
        for (int j = 0; j < 9; j++) { val[j] = NEG; idx[j] = 0; }

#pragma unroll
        for (int e = 0; e < N_EXP; e++) {
            float cv = row[e] * SCALE + bias_sm[e];
            int   ci = e;
#pragma unroll
            for (int j = 0; j < 9; j++) {
                if (cv > val[j]) {
                    float tv = val[j]; val[j] = cv; cv = tv;
                    int   ti = idx[j]; idx[j] = ci; ci = ti;
                }
            }
        }

        float ming = val[0] - val[1];
#pragma unroll
        for (int j = 1; j < 8; j++) ming = fminf(ming, val[j] - val[j + 1]);

        float orig[TOP_K];
#pragma unroll
        for (int j = 0; j < TOP_K; j++) orig[j] = val[j] - bias_sm[idx[j]];
        float m = orig[0];
#pragma unroll
        for (int j = 1; j < TOP_K; j++) m = fmaxf(m, orig[j]);
        float ex[TOP_K], ssum = 0.0f;
#pragma unroll
        for (int j = 0; j < TOP_K; j++) { ex[j] = __expf(orig[j] - m); ssum += ex[j]; }
        float inv = 1.0f / ssum;

        float* wout = out + (size_t)tok * TOP_K;
        float* iout = out + (size_t)T * TOP_K + (size_t)tok * TOP_K;
#pragma unroll
        for (int j = 0; j < TOP_K; j++) { wout[j] = ex[j] * inv; iout[j] = (float)idx[j]; }

        if (ming < EPS) {
            int p = atomicAdd(&g_flag_count, 1);
            if (p < MAX_T) g_flags[p] = tok;
        }
    }
}

// ---------------------------------------------------------------------------
// Fixup stage 1 (panel-parallel, proven): block = (batch of 32 tokens,
// panel of 512 k). Exact serial FFMA chain ascending k within panel.
// ---------------------------------------------------------------------------
#define FB 32
#define XPITCH 34
__global__ void __launch_bounds__(256) fixup_panel_kernel(
    const float* __restrict__ x, const float* __restrict__ W)
{
    __shared__ __align__(16) float Wp[64][68];
    __shared__ __align__(16) float Xt[64][XPITCH];

    const int t = threadIdx.x;

    int F = g_flag_count;
    if (F > MAX_T) F = MAX_T;
    const int nb = (F + FB - 1) / FB;

    const int e0 = (t & 15) * 4;
    const int tq = t >> 4;
    const int sx_tok = t >> 3;
    const int sx_k0  = (t & 7) * 8;

    for (int it = blockIdx.x; it < nb * 4; it += gridDim.x) {
        const int b = it >> 2;
        const int p = it & 3;

        float accP[2][4];
#pragma unroll
        for (int i = 0; i < 2; i++)
#pragma unroll
            for (int q = 0; q < 4; q++) accP[i][q] = 0.f;

        for (int kc = p * 8; kc < p * 8 + 8; kc++) {
            __syncthreads();
            {
                int s2 = b * FB + sx_tok;
                int gt = g_flags[(s2 < F) ? s2 : (F - 1)];
                const float* xp = x + (size_t)gt * D_MODEL + kc * 64 + sx_k0;
                float4 v0 = *reinterpret_cast<const float4*>(xp);
                float4 v1 = *reinterpret_cast<const float4*>(xp + 4);
                Xt[sx_k0 + 0][sx_tok] = v0.x; Xt[sx_k0 + 1][sx_tok] = v0.y;
                Xt[sx_k0 + 2][sx_tok] = v0.z; Xt[sx_k0 + 3][sx_tok] = v0.w;
                Xt[sx_k0 + 4][sx_tok] = v1.x; Xt[sx_k0 + 5][sx_tok] = v1.y;
                Xt[sx_k0 + 6][sx_tok] = v1.z; Xt[sx_k0 + 7][sx_tok] = v1.w;
            }
#pragma unroll
            for (int j = 0; j < 4; j++) {
                int idx = t + 256 * j;
                int xe  = idx >> 4;
                int kq  = (idx & 15) * 4;
                float4 w = *reinterpret_cast<const float4*>(
                    W + (size_t)xe * D_MODEL + kc * 64 + kq);
                Wp[kq + 0][xe] = w.x;
                Wp[kq + 1][xe] = w.y;
                Wp[kq + 2][xe] = w.z;
                Wp[kq + 3][xe] = w.w;
            }
            __syncthreads();
#pragma unroll 4
            for (int k = 0; k < 64; k++) {
                float4 wvv = *reinterpret_cast<const float4*>(&Wp[k][e0]);
                float2 xvv = *reinterpret_cast<const float2*>(&Xt[k][tq * 2]);
                accP[0][0] = __fmaf_rn(xvv.x, wvv.x, accP[0][0]);
                accP[0][1] = __fmaf_rn(xvv.x, wvv.y, accP[0][1]);
                accP[0][2] = __fmaf_rn(xvv.x, wvv.z, accP[0][2]);
                accP[0][3] = __fmaf_rn(xvv.x, wvv.w, accP[0][3]);
                accP[1][0] = __fmaf_rn(xvv.y, wvv.x, accP[1][0]);
                accP[1][1] = __fmaf_rn(xvv.y, wvv.y, accP[1][1]);
                accP[1][2] = __fmaf_rn(xvv.y, wvv.z, accP[1][2]);
                accP[1][3] = __fmaf_rn(xvv.y, wvv.w, accP[1][3]);
            }
        }
#pragma unroll
        for (int i = 0; i < 2; i++) {
            float4 v = make_float4(accP[i][0], accP[i][1], accP[i][2], accP[i][3]);
            *reinterpret_cast<float4*>(
                &g_partial[(((size_t)b * FB + tq * 2 + i) * 4 + p) * 64 + e0]) = v;
        }
        __syncthreads();
    }
}

// ---------------------------------------------------------------------------
// Fixup stage 2 (combine, proven): sum 4 panel partials ascending
// (__fadd_rn), x SCALE, exact top-k, softmax, write. Ticket resets counter.
// ---------------------------------------------------------------------------
__global__ void __launch_bounds__(256) fixup_combine_kernel(
    const float* __restrict__ bias, float* __restrict__ out, int T)
{
    __shared__ float Lg[FB][66];
    __shared__ float bias_f[N_EXP];

    const int t = threadIdx.x;
    if (t < N_EXP) bias_f[t] = bias[t];

    int F = g_flag_count;
    if (F > MAX_T) F = MAX_T;
    const int nb = (F + FB - 1) / FB;

    const int tok_s = t >> 3;
    const int eg    = (t & 7) * 8;

    for (int b = blockIdx.x; b < nb; b += gridDim.x) {
        __syncthreads();
#pragma unroll
        for (int u = 0; u < 2; u++) {
            int e = eg + u * 4;
            const float* gp =
                &g_partial[(((size_t)b * FB + tok_s) * 4 + 0) * 64 + e];
            float4 p0 = *reinterpret_cast<const float4*>(gp);
            float4 p1 = *reinterpret_cast<const float4*>(gp + 64);
            float4 p2 = *reinterpret_cast<const float4*>(gp + 128);
            float4 p3 = *reinterpret_cast<const float4*>(gp + 192);
            Lg[tok_s][e + 0] = __fmul_rn(__fadd_rn(__fadd_rn(__fadd_rn(p0.x, p1.x), p2.x), p3.x), SCALE);
            Lg[tok_s][e + 1] = __fmul_rn(__fadd_rn(__fadd_rn(__fadd_rn(p0.y, p1.y), p2.y), p3.y), SCALE);
            Lg[tok_s][e + 2] = __fmul_rn(__fadd_rn(__fadd_rn(__fadd_rn(p0.z, p1.z), p2.z), p3.z), SCALE);
            Lg[tok_s][e + 3] = __fmul_rn(__fadd_rn(__fadd_rn(__fadd_rn(p0.w, p1.w), p2.w), p3.w), SCALE);
        }
        __syncthreads();

        if (t < FB && b * FB + t < F) {
            const int tok = g_flags[b * FB + t];
            const float* row = &Lg[t][0];
            unsigned long long used = 0ull;
            int sel[TOP_K]; float sl[TOP_K];
            for (int k = 0; k < TOP_K; k++) {
                float best = -3.0e38f; int bi = 0;
                for (int e = 0; e < N_EXP; e++) {
                    if ((used >> e) & 1ull) continue;
                    float bv = __fadd_rn(row[e], bias_f[e]);
                    if (bv > best) { best = bv; bi = e; }
                }
                sel[k] = bi; sl[k] = row[bi];
                used |= (1ull << bi);
            }
            float m = sl[0];
            for (int k = 1; k < TOP_K; k++) m = fmaxf(m, sl[k]);
            float ex[TOP_K], s = 0.0f;
            for (int k = 0; k < TOP_K; k++) { ex[k] = __expf(sl[k] - m); s += ex[k]; }
            float inv = 1.0f / s;
            for (int k = 0; k < TOP_K; k++) {
                out[(size_t)tok * TOP_K + k] = ex[k] * inv;
                out[(size_t)T * TOP_K + (size_t)tok * TOP_K + k] = (float)sel[k];
            }
        }
    }

    __syncthreads();
    if (t == 0) {
        __threadfence();
        int ticket = atomicAdd(&g_done_count, 1);
        if (ticket == (int)gridDim.x - 1) {
            g_flag_count = 0;
            g_done_count = 0;
            __threadfence();
        }
    }
}

// ---------------------------------------------------------------------------
extern "C" void kernel_launch(void* const* d_in, const int* in_sizes, int n_in,
                              void* d_out, int out_size)
{
    const float* x    = (const float*)d_in[0];
    const float* W    = (const float*)d_in[1];
    const float* bias = (const float*)d_in[2];
    float* out        = (float*)d_out;

    int T = in_sizes[0] / D_MODEL;  // 16384

    router_mma_kernel<<<T / CTA_TOK, 256>>>(x, W, bias, out, T);
    fixup_panel_kernel<<<1184, 256>>>(x, W);
    fixup_combine_kernel<<<256, 256>>>(bias, out, T);
}

// round 16
// speedup vs baseline: 1.2329x; 1.2329x over previous
#include <cuda_runtime.h>
#include <cuda_fp16.h>
#include <cstdint>
#include <math.h>

#define D_MODEL 2048
#define N_EXP   64
#define TOP_K   8
#define SCALE   0.022097086912079608f
#define EPS     4.2e-5f
#define MAX_T   16384
#define CTA_TOK 64
#define NCHUNK  32            // 2048 / 64
#define WPITCH  144           // bytes per 64-half W smem row (ldmatrix-friendly)
#define TPITCH  528           // bytes per 16x16 A-fragment tile (bank-rotated)
#define LROW    66

// ---- device globals (no allocations allowed; zero-initialized at load) -----
__device__ int   g_flag_count;   // 0 at call 1; reset by combine ticket after
__device__ int   g_done_count;
__device__ int   g_flags[MAX_T];
// panel partials: [batch(<=512)][tok 32][panel 4][exp 64]
__device__ float g_partial[(MAX_T / 32) * 32 * 4 * 64];

// ---- fp16 MMA ---------------------------------------------------------------
static __device__ __forceinline__ void mma16816(float* d, const uint32_t* a,
                                                uint32_t b0, uint32_t b1) {
    asm volatile(
        "mma.sync.aligned.m16n8k16.row.col.f32.f16.f16.f32 "
        "{%0,%1,%2,%3}, {%4,%5,%6,%7}, {%8,%9}, {%0,%1,%2,%3};"
        : "+f"(d[0]), "+f"(d[1]), "+f"(d[2]), "+f"(d[3])
        : "r"(a[0]), "r"(a[1]), "r"(a[2]), "r"(a[3]), "r"(b0), "r"(b1));
}

static __device__ __forceinline__ void ldmatrix_x4(
    uint32_t& r0, uint32_t& r1, uint32_t& r2, uint32_t& r3, uint32_t saddr) {
    asm volatile(
        "ldmatrix.sync.aligned.m8n8.x4.shared.b16 {%0,%1,%2,%3}, [%4];"
        : "=r"(r0), "=r"(r1), "=r"(r2), "=r"(r3) : "r"(saddr));
}

static __device__ __forceinline__ uint32_t cvt2(float a, float b) {
    __half2 h = __floats2half2_rn(a, b);
    return *reinterpret_cast<uint32_t*>(&h);
}

// ---------------------------------------------------------------------------
// Main: x(fp16) x W(fp16, converted in-kernel) HMMA. A tile staged
// fragment-permuted (one LDS.128 per A frag); W staged PLAIN k-consecutive
// (pitch 144), COALESCED (2 experts x 256B per warp, nL=4), B frags via
// ldmatrix.x4. Fused top-9 / flag / softmax. CTA = 256 thr / 8 warps.
// ---------------------------------------------------------------------------
#define SM_A(s)  ((s) * (16 * TPITCH))                 // 2 x 8448 = 16896
#define SM_W(s)  (16896 + (s) * (64 * WPITCH))         // 2 x 9216 = 18432
#define SM_BIAS  35328
#define SM_TOT   35584

__global__ void __launch_bounds__(256, 2)
router_mma_kernel(const float* __restrict__ x, const float* __restrict__ W,
                  const float* __restrict__ bias, float* __restrict__ out, int T)
{
    __shared__ __align__(16) char sm[SM_TOT];

    const int tid  = threadIdx.x;
    const int wid  = tid >> 5;
    const int lane = tid & 31;
    const int tg   = wid >> 1;
    const int eh   = wid & 1;
    const int tokBase = blockIdx.x * CTA_TOK;
    const int wtok = tokBase + tg * 16;

    float* bias_sm = reinterpret_cast<float*>(sm + SM_BIAS);
    if (tid < N_EXP) bias_sm[tid] = bias[tid];

    const int n4 = lane >> 2;
    const int q4 = lane & 3;
    const int cp2 = q4 << 1;

    // ---- A writer mapping (proven): 4 float4 per thread, coalesced ---------
    int arow[4], adst0[4], adst1[4];
#pragma unroll
    for (int j = 0; j < 4; j++) {
        int u  = tid + 256 * j;
        int r  = u >> 4;
        int k0 = (u & 15) * 4;
        int tgw = r >> 4, rr = r & 15, rA = rr & 7, hifl = rr >> 3;
        int ks = k0 >> 4, kk = k0 & 15, khi = kk >> 3, qa = (kk & 7) >> 1;
        arow[j]  = r;
        int tbase = (tgw * 4 + ks) * TPITCH + (hifl + khi * 2) * 4;
        adst0[j] = tbase + (rA * 4 + qa) * 16;
        adst1[j] = tbase + (rA * 4 + qa + 1) * 16;
    }
    const int ak0_0 = (tid & 15) * 4;

    // ---- W mapping (coalesced): idx = tid+256j -> e = idx>>4, kq = (idx&15)*4
    int wgoff[4], wsoff[4];
#pragma unroll
    for (int j = 0; j < 4; j++) {
        int idx = tid + 256 * j;
        int e   = idx >> 4;
        int kq  = (idx & 15) * 4;
        wgoff[j] = e * D_MODEL + kq;          // float offset (+ c*64 later)
        wsoff[j] = e * WPITCH + kq * 2;       // byte offset in smem plane
    }

    // ldmatrix lane address component: matrix id m = lane>>3
    const uint32_t lm_lane_off =
        (uint32_t)((((lane >> 4) & 1) * 8 + (lane & 7)) * WPITCH +
                   ((lane >> 3) & 1) * 16);

    auto loadA = [&](int c, float4* av) {
#pragma unroll
        for (int j = 0; j < 4; j++)
            av[j] = *reinterpret_cast<const float4*>(
                x + (size_t)(tokBase + arow[j]) * D_MODEL + c * 64 + ak0_0);
    };
    auto storeA = [&](int s, const float4* av) {
#pragma unroll
        for (int j = 0; j < 4; j++) {
            *reinterpret_cast<uint32_t*>(sm + SM_A(s) + adst0[j]) =
                cvt2(av[j].x, av[j].y);
            *reinterpret_cast<uint32_t*>(sm + SM_A(s) + adst1[j]) =
                cvt2(av[j].z, av[j].w);
        }
    };
    auto loadW = [&](int c, float4* wv) {
#pragma unroll
        for (int j = 0; j < 4; j++)
            wv[j] = *reinterpret_cast<const float4*>(W + wgoff[j] + c * 64);
    };
    auto storeW = [&](int s, const float4* wv) {
#pragma unroll
        for (int j = 0; j < 4; j++) {
            uint2 o;
            o.x = cvt2(wv[j].x, wv[j].y);
            o.y = cvt2(wv[j].z, wv[j].w);
            *reinterpret_cast<uint2*>(&sm[SM_W(s) + wsoff[j]]) = o;
        }
    };

    // prologue: stage chunk 0
    float4 av[4], wv[4];
    loadA(0, av);
    loadW(0, wv);
    storeA(0, av);
    storeW(0, wv);
    __syncthreads();

    float dh[4][4];
#pragma unroll
    for (int j = 0; j < 4; j++)
#pragma unroll
        for (int q = 0; q < 4; q++) dh[j][q] = 0.0f;

    for (int c = 0; c < NCHUNK; c++) {
        const int buf = c & 1;

        if (c + 1 < NCHUNK) {
            loadA(c + 1, av);
            loadW(c + 1, wv);
        }

        const char* AS = sm + SM_A(buf);
        const uint32_t WSH =
            (uint32_t)__cvta_generic_to_shared(sm + SM_W(buf)) +
            (uint32_t)(eh * 32 * WPITCH) + lm_lane_off;
#pragma unroll
        for (int ks = 0; ks < 4; ks++) {
            uint4 af = *reinterpret_cast<const uint4*>(
                AS + (tg * 4 + ks) * TPITCH + lane * 16);
            uint32_t a[4] = {af.x, af.y, af.z, af.w};
            uint32_t b0, b1, b2, b3;
            ldmatrix_x4(b0, b1, b2, b3, WSH + ks * 32);
            mma16816(dh[0], a, b0, b1);
            mma16816(dh[1], a, b2, b3);
            ldmatrix_x4(b0, b1, b2, b3, WSH + 16 * WPITCH + ks * 32);
            mma16816(dh[2], a, b0, b1);
            mma16816(dh[3], a, b2, b3);
        }
        if (c + 1 < NCHUNK) {
            storeA(buf ^ 1, av);
            storeW(buf ^ 1, wv);
        }
        __syncthreads();
    }

    // ---- epilogue: spill logits into W region, per-lane top-9 --------------
    float* lw = reinterpret_cast<float*>(sm + SM_W(0)) + tg * 16 * LROW;
#pragma unroll
    for (int j = 0; j < 4; j++) {
        int col = eh * 32 + j * 8 + cp2;
        lw[n4 * LROW + col]           = dh[j][0];
        lw[n4 * LROW + col + 1]       = dh[j][1];
        lw[(n4 + 8) * LROW + col]     = dh[j][2];
        lw[(n4 + 8) * LROW + col + 1] = dh[j][3];
    }
    __syncthreads();

    if (eh == 0 && lane < 16) {
        const int tok = wtok + lane;
        const float* row = lw + lane * LROW;
        const float NEG = -3.0e38f;

        float val[9]; int idx[9];
#pragma unroll
        for (int j = 0; j < 9; j++) { val[j] = NEG; idx[j] = 0; }

#pragma unroll
        for (int e = 0; e < N_EXP; e++) {
            float cv = row[e] * SCALE + bias_sm[e];
            int   ci = e;
#pragma unroll
            for (int j = 0; j < 9; j++) {
                if (cv > val[j]) {
                    float tv = val[j]; val[j] = cv; cv = tv;
                    int   ti = idx[j]; idx[j] = ci; ci = ti;
                }
            }
        }

        float ming = val[0] - val[1];
#pragma unroll
        for (int j = 1; j < 8; j++) ming = fminf(ming, val[j] - val[j + 1]);

        float orig[TOP_K];
#pragma unroll
        for (int j = 0; j < TOP_K; j++) orig[j] = val[j] - bias_sm[idx[j]];
        float m = orig[0];
#pragma unroll
        for (int j = 1; j < TOP_K; j++) m = fmaxf(m, orig[j]);
        float ex[TOP_K], ssum = 0.0f;
#pragma unroll
        for (int j = 0; j < TOP_K; j++) { ex[j] = __expf(orig[j] - m); ssum += ex[j]; }
        float inv = 1.0f / ssum;

        float* wout = out + (size_t)tok * TOP_K;
        float* iout = out + (size_t)T * TOP_K + (size_t)tok * TOP_K;
#pragma unroll
        for (int j = 0; j < TOP_K; j++) { wout[j] = ex[j] * inv; iout[j] = (float)idx[j]; }

        if (ming < EPS) {
            int p = atomicAdd(&g_flag_count, 1);
            if (p < MAX_T) g_flags[p] = tok;
        }
    }
}

// ---------------------------------------------------------------------------
// Fixup stage 1 (panel-parallel, proven): block = (batch of 32 tokens,
// panel of 512 k). Exact serial FFMA chain ascending k within panel.
// ---------------------------------------------------------------------------
#define FB 32
#define XPITCH 34
__global__ void __launch_bounds__(256) fixup_panel_kernel(
    const float* __restrict__ x, const float* __restrict__ W)
{
    __shared__ __align__(16) float Wp[64][68];
    __shared__ __align__(16) float Xt[64][XPITCH];

    const int t = threadIdx.x;

    int F = g_flag_count;
    if (F > MAX_T) F = MAX_T;
    const int nb = (F + FB - 1) / FB;

    const int e0 = (t & 15) * 4;
    const int tq = t >> 4;
    const int sx_tok = t >> 3;
    const int sx_k0  = (t & 7) * 8;

    for (int it = blockIdx.x; it < nb * 4; it += gridDim.x) {
        const int b = it >> 2;
        const int p = it & 3;

        float accP[2][4];
#pragma unroll
        for (int i = 0; i < 2; i++)
#pragma unroll
            for (int q = 0; q < 4; q++) accP[i][q] = 0.f;

        for (int kc = p * 8; kc < p * 8 + 8; kc++) {
            __syncthreads();
            {
                int s2 = b * FB + sx_tok;
                int gt = g_flags[(s2 < F) ? s2 : (F - 1)];
                const float* xp = x + (size_t)gt * D_MODEL + kc * 64 + sx_k0;
                float4 v0 = *reinterpret_cast<const float4*>(xp);
                float4 v1 = *reinterpret_cast<const float4*>(xp + 4);
                Xt[sx_k0 + 0][sx_tok] = v0.x; Xt[sx_k0 + 1][sx_tok] = v0.y;
                Xt[sx_k0 + 2][sx_tok] = v0.z; Xt[sx_k0 + 3][sx_tok] = v0.w;
                Xt[sx_k0 + 4][sx_tok] = v1.x; Xt[sx_k0 + 5][sx_tok] = v1.y;
                Xt[sx_k0 + 6][sx_tok] = v1.z; Xt[sx_k0 + 7][sx_tok] = v1.w;
            }
#pragma unroll
            for (int j = 0; j < 4; j++) {
                int idx = t + 256 * j;
                int xe  = idx >> 4;
                int kq  = (idx & 15) * 4;
                float4 w = *reinterpret_cast<const float4*>(
                    W + (size_t)xe * D_MODEL + kc * 64 + kq);
                Wp[kq + 0][xe] = w.x;
                Wp[kq + 1][xe] = w.y;
                Wp[kq + 2][xe] = w.z;
                Wp[kq + 3][xe] = w.w;
            }
            __syncthreads();
#pragma unroll 4
            for (int k = 0; k < 64; k++) {
                float4 wvv = *reinterpret_cast<const float4*>(&Wp[k][e0]);
                float2 xvv = *reinterpret_cast<const float2*>(&Xt[k][tq * 2]);
                accP[0][0] = __fmaf_rn(xvv.x, wvv.x, accP[0][0]);
                accP[0][1] = __fmaf_rn(xvv.x, wvv.y, accP[0][1]);
                accP[0][2] = __fmaf_rn(xvv.x, wvv.z, accP[0][2]);
                accP[0][3] = __fmaf_rn(xvv.x, wvv.w, accP[0][3]);
                accP[1][0] = __fmaf_rn(xvv.y, wvv.x, accP[1][0]);
                accP[1][1] = __fmaf_rn(xvv.y, wvv.y, accP[1][1]);
                accP[1][2] = __fmaf_rn(xvv.y, wvv.z, accP[1][2]);
                accP[1][3] = __fmaf_rn(xvv.y, wvv.w, accP[1][3]);
            }
        }
#pragma unroll
        for (int i = 0; i < 2; i++) {
            float4 v = make_float4(accP[i][0], accP[i][1], accP[i][2], accP[i][3]);
            *reinterpret_cast<float4*>(
                &g_partial[(((size_t)b * FB + tq * 2 + i) * 4 + p) * 64 + e0]) = v;
        }
        __syncthreads();
    }
}

// ---------------------------------------------------------------------------
// Fixup stage 2 (combine, proven): sum 4 panel partials ascending
// (__fadd_rn), x SCALE, exact top-k, softmax, write. Ticket resets counter.
// ---------------------------------------------------------------------------
__global__ void __launch_bounds__(256) fixup_combine_kernel(
    const float* __restrict__ bias, float* __restrict__ out, int T)
{
    __shared__ float Lg[FB][66];
    __shared__ float bias_f[N_EXP];

    const int t = threadIdx.x;
    if (t < N_EXP) bias_f[t] = bias[t];

    int F = g_flag_count;
    if (F > MAX_T) F = MAX_T;
    const int nb = (F + FB - 1) / FB;

    const int tok_s = t >> 3;
    const int eg    = (t & 7) * 8;

    for (int b = blockIdx.x; b < nb; b += gridDim.x) {
        __syncthreads();
#pragma unroll
        for (int u = 0; u < 2; u++) {
            int e = eg + u * 4;
            const float* gp =
                &g_partial[(((size_t)b * FB + tok_s) * 4 + 0) * 64 + e];
            float4 p0 = *reinterpret_cast<const float4*>(gp);
            float4 p1 = *reinterpret_cast<const float4*>(gp + 64);
            float4 p2 = *reinterpret_cast<const float4*>(gp + 128);
            float4 p3 = *reinterpret_cast<const float4*>(gp + 192);
            Lg[tok_s][e + 0] = __fmul_rn(__fadd_rn(__fadd_rn(__fadd_rn(p0.x, p1.x), p2.x), p3.x), SCALE);
            Lg[tok_s][e + 1] = __fmul_rn(__fadd_rn(__fadd_rn(__fadd_rn(p0.y, p1.y), p2.y), p3.y), SCALE);
            Lg[tok_s][e + 2] = __fmul_rn(__fadd_rn(__fadd_rn(__fadd_rn(p0.z, p1.z), p2.z), p3.z), SCALE);
            Lg[tok_s][e + 3] = __fmul_rn(__fadd_rn(__fadd_rn(__fadd_rn(p0.w, p1.w), p2.w), p3.w), SCALE);
        }
        __syncthreads();

        if (t < FB && b * FB + t < F) {
            const int tok = g_flags[b * FB + t];
            const float* row = &Lg[t][0];
            unsigned long long used = 0ull;
            int sel[TOP_K]; float sl[TOP_K];
            for (int k = 0; k < TOP_K; k++) {
                float best = -3.0e38f; int bi = 0;
                for (int e = 0; e < N_EXP; e++) {
                    if ((used >> e) & 1ull) continue;
                    float bv = __fadd_rn(row[e], bias_f[e]);
                    if (bv > best) { best = bv; bi = e; }
                }
                sel[k] = bi; sl[k] = row[bi];
                used |= (1ull << bi);
            }
            float m = sl[0];
            for (int k = 1; k < TOP_K; k++) m = fmaxf(m, sl[k]);
            float ex[TOP_K], s = 0.0f;
            for (int k = 0; k < TOP_K; k++) { ex[k] = __expf(sl[k] - m); s += ex[k]; }
            float inv = 1.0f / s;
            for (int k = 0; k < TOP_K; k++) {
                out[(size_t)tok * TOP_K + k] = ex[k] * inv;
                out[(size_t)T * TOP_K + (size_t)tok * TOP_K + k] = (float)sel[k];
            }
        }
    }

    __syncthreads();
    if (t == 0) {
        __threadfence();
        int ticket = atomicAdd(&g_done_count, 1);
        if (ticket == (int)gridDim.x - 1) {
            g_flag_count = 0;
            g_done_count = 0;
            __threadfence();
        }
    }
}

// ---------------------------------------------------------------------------
extern "C" void kernel_launch(void* const* d_in, const int* in_sizes, int n_in,
                              void* d_out, int out_size)
{
    const float* x    = (const float*)d_in[0];
    const float* W    = (const float*)d_in[1];
    const float* bias = (const float*)d_in[2];
    float* out        = (float*)d_out;

    int T = in_sizes[0] / D_MODEL;  // 16384

    router_mma_kernel<<<T / CTA_TOK, 256>>>(x, W, bias, out, T);
    fixup_panel_kernel<<<592, 256>>>(x, W);
    fixup_combine_kernel<<<128, 256>>>(bias, out, T);
}

// round 17
// speedup vs baseline: 1.3984x; 1.1342x over previous
#include <cuda_runtime.h>
#include <cuda_fp16.h>
#include <cstdint>
#include <math.h>

#define D_MODEL 2048
#define N_EXP   64
#define TOP_K   8
#define SCALE   0.022097086912079608f
#define EPS     2e-6f
#define MAX_T   16384
#define CTA_TOK 64
#define NCHUNK  32            // 2048 / 64
#define WPITCH  144           // bytes per 64-half W smem row (ldmatrix-friendly)
#define TPITCH  528           // bytes per 16x16 A-fragment tile (bank-rotated)
#define LROW    66
#define INV_LOSCALE 0.0009765625f   // 1/1024

// ---- device globals (no allocations allowed; zero-initialized at load) -----
__device__ int   g_flag_count;   // 0 at call 1; reset by combine ticket after
__device__ int   g_done_count;
__device__ int   g_flags[MAX_T];
// panel partials: [batch(<=512)][tok 32][panel 4][exp 64]
__device__ float g_partial[(MAX_T / 32) * 32 * 4 * 64];

// ---- fp16 MMA ---------------------------------------------------------------
static __device__ __forceinline__ void mma16816(float* d, const uint32_t* a,
                                                uint32_t b0, uint32_t b1) {
    asm volatile(
        "mma.sync.aligned.m16n8k16.row.col.f32.f16.f16.f32 "
        "{%0,%1,%2,%3}, {%4,%5,%6,%7}, {%8,%9}, {%0,%1,%2,%3};"
        : "+f"(d[0]), "+f"(d[1]), "+f"(d[2]), "+f"(d[3])
        : "r"(a[0]), "r"(a[1]), "r"(a[2]), "r"(a[3]), "r"(b0), "r"(b1));
}

static __device__ __forceinline__ void ldmatrix_x4(
    uint32_t& r0, uint32_t& r1, uint32_t& r2, uint32_t& r3, uint32_t saddr) {
    asm volatile(
        "ldmatrix.sync.aligned.m8n8.x4.shared.b16 {%0,%1,%2,%3}, [%4];"
        : "=r"(r0), "=r"(r1), "=r"(r2), "=r"(r3) : "r"(saddr));
}

static __device__ __forceinline__ uint32_t cvt2(float a, float b) {
    __half2 h = __floats2half2_rn(a, b);
    return *reinterpret_cast<uint32_t*>(&h);
}
// hi fp16 pair + residual (x1024) fp16 pair (proven in R13)
static __device__ __forceinline__ void split2(float a, float b,
                                              uint32_t& hi, uint32_t& lo) {
    __half2 h = __floats2half2_rn(a, b);
    hi = *reinterpret_cast<uint32_t*>(&h);
    float ra = (a - __half2float(h.x)) * 1024.0f;
    float rb = (b - __half2float(h.y)) * 1024.0f;
    lo = cvt2(ra, rb);
}

// ---------------------------------------------------------------------------
// Main: 3-pass fp16-split HMMA (xh*Wh + xh*Wl + xl*Wh; lo planes x1024) on
// the R16-optimized staging: coalesced LDG, fragment-permuted A (LDS.128
// per frag), plain-k W planes + ldmatrix.x4 B frags. Fused top-9 / flag /
// softmax. CTA = 256 thr / 8 warps; dynamic SMEM 71KB, 2 CTAs/SM.
// ---------------------------------------------------------------------------
#define SM_AH(s)  ((s) * (16 * TPITCH))                 // 2 x 8448
#define SM_AL(s)  (16896 + (s) * (16 * TPITCH))         // 2 x 8448
#define SM_WH(s)  (33792 + (s) * (64 * WPITCH))         // 2 x 9216
#define SM_WL(s)  (52224 + (s) * (64 * WPITCH))         // 2 x 9216
#define SM_BIAS   70656
#define SM_TOT    70912

__global__ void __launch_bounds__(256, 2)
router_mma_kernel(const float* __restrict__ x, const float* __restrict__ W,
                  const float* __restrict__ bias, float* __restrict__ out, int T)
{
    extern __shared__ __align__(16) char sm[];

    const int tid  = threadIdx.x;
    const int wid  = tid >> 5;
    const int lane = tid & 31;
    const int tg   = wid >> 1;
    const int eh   = wid & 1;
    const int tokBase = blockIdx.x * CTA_TOK;
    const int wtok = tokBase + tg * 16;

    float* bias_sm = reinterpret_cast<float*>(sm + SM_BIAS);
    if (tid < N_EXP) bias_sm[tid] = bias[tid];

    const int n4 = lane >> 2;
    const int q4 = lane & 3;
    const int cp2 = q4 << 1;

    // ---- A writer mapping (proven): 4 float4 per thread, coalesced ---------
    int arow[4], adst0[4], adst1[4];
#pragma unroll
    for (int j = 0; j < 4; j++) {
        int u  = tid + 256 * j;
        int r  = u >> 4;
        int k0 = (u & 15) * 4;
        int tgw = r >> 4, rr = r & 15, rA = rr & 7, hifl = rr >> 3;
        int ks = k0 >> 4, kk = k0 & 15, khi = kk >> 3, qa = (kk & 7) >> 1;
        arow[j]  = r;
        int tbase = (tgw * 4 + ks) * TPITCH + (hifl + khi * 2) * 4;
        adst0[j] = tbase + (rA * 4 + qa) * 16;
        adst1[j] = tbase + (rA * 4 + qa + 1) * 16;
    }
    const int ak0_0 = (tid & 15) * 4;

    // ---- W mapping (proven, coalesced): e = idx>>4, kq = (idx&15)*4 --------
    int wgoff[4], wsoff[4];
#pragma unroll
    for (int j = 0; j < 4; j++) {
        int idx = tid + 256 * j;
        int e   = idx >> 4;
        int kq  = (idx & 15) * 4;
        wgoff[j] = e * D_MODEL + kq;
        wsoff[j] = e * WPITCH + kq * 2;
    }

    const uint32_t lm_lane_off =
        (uint32_t)((((lane >> 4) & 1) * 8 + (lane & 7)) * WPITCH +
                   ((lane >> 3) & 1) * 16);

    auto loadA = [&](int c, float4* av) {
#pragma unroll
        for (int j = 0; j < 4; j++)
            av[j] = *reinterpret_cast<const float4*>(
                x + (size_t)(tokBase + arow[j]) * D_MODEL + c * 64 + ak0_0);
    };
    auto storeA = [&](int s, const float4* av) {
#pragma unroll
        for (int j = 0; j < 4; j++) {
            uint32_t h01, l01, h23, l23;
            split2(av[j].x, av[j].y, h01, l01);
            split2(av[j].z, av[j].w, h23, l23);
            *reinterpret_cast<uint32_t*>(sm + SM_AH(s) + adst0[j]) = h01;
            *reinterpret_cast<uint32_t*>(sm + SM_AH(s) + adst1[j]) = h23;
            *reinterpret_cast<uint32_t*>(sm + SM_AL(s) + adst0[j]) = l01;
            *reinterpret_cast<uint32_t*>(sm + SM_AL(s) + adst1[j]) = l23;
        }
    };
    auto loadW = [&](int c, float4* wv) {
#pragma unroll
        for (int j = 0; j < 4; j++)
            wv[j] = *reinterpret_cast<const float4*>(W + wgoff[j] + c * 64);
    };
    auto storeW = [&](int s, const float4* wv) {
#pragma unroll
        for (int j = 0; j < 4; j++) {
            uint32_t h0, l0, h1, l1;
            split2(wv[j].x, wv[j].y, h0, l0);
            split2(wv[j].z, wv[j].w, h1, l1);
            *reinterpret_cast<uint2*>(&sm[SM_WH(s) + wsoff[j]]) = make_uint2(h0, h1);
            *reinterpret_cast<uint2*>(&sm[SM_WL(s) + wsoff[j]]) = make_uint2(l0, l1);
        }
    };

    // prologue: stage chunk 0
    float4 av[4], wv[4];
    loadA(0, av);
    loadW(0, wv);
    storeA(0, av);
    storeW(0, wv);
    __syncthreads();

    float dh[4][4], dl[4][4];
#pragma unroll
    for (int j = 0; j < 4; j++)
#pragma unroll
        for (int q = 0; q < 4; q++) { dh[j][q] = 0.0f; dl[j][q] = 0.0f; }

    for (int c = 0; c < NCHUNK; c++) {
        const int buf = c & 1;

        if (c + 1 < NCHUNK) {
            loadA(c + 1, av);
            loadW(c + 1, wv);
        }

        const char* AH = sm + SM_AH(buf);
        const char* AL = sm + SM_AL(buf);
        const uint32_t ehoff = (uint32_t)(eh * 32 * WPITCH) + lm_lane_off;
        const uint32_t WSHH =
            (uint32_t)__cvta_generic_to_shared(sm + SM_WH(buf)) + ehoff;
        const uint32_t WSHL =
            (uint32_t)__cvta_generic_to_shared(sm + SM_WL(buf)) + ehoff;
#pragma unroll
        for (int ks = 0; ks < 4; ks++) {
            const uint32_t aoff = (uint32_t)((tg * 4 + ks) * TPITCH + lane * 16);
            uint4 afh = *reinterpret_cast<const uint4*>(AH + aoff);
            uint4 afl = *reinterpret_cast<const uint4*>(AL + aoff);
            uint32_t ah[4] = {afh.x, afh.y, afh.z, afh.w};
            uint32_t al[4] = {afl.x, afl.y, afl.z, afl.w};

            uint32_t bh0, bh1, bh2, bh3, bl0, bl1, bl2, bl3;
            // expert octets {0,1} of this half
            ldmatrix_x4(bh0, bh1, bh2, bh3, WSHH + ks * 32);
            ldmatrix_x4(bl0, bl1, bl2, bl3, WSHL + ks * 32);
            mma16816(dh[0], ah, bh0, bh1);
            mma16816(dh[1], ah, bh2, bh3);
            mma16816(dl[0], ah, bl0, bl1);
            mma16816(dl[1], ah, bl2, bl3);
            mma16816(dl[0], al, bh0, bh1);
            mma16816(dl[1], al, bh2, bh3);
            // expert octets {2,3}
            ldmatrix_x4(bh0, bh1, bh2, bh3, WSHH + 16 * WPITCH + ks * 32);
            ldmatrix_x4(bl0, bl1, bl2, bl3, WSHL + 16 * WPITCH + ks * 32);
            mma16816(dh[2], ah, bh0, bh1);
            mma16816(dh[3], ah, bh2, bh3);
            mma16816(dl[2], ah, bl0, bl1);
            mma16816(dl[3], ah, bl2, bl3);
            mma16816(dl[2], al, bh0, bh1);
            mma16816(dl[3], al, bh2, bh3);
        }
        if (c + 1 < NCHUNK) {
            storeA(buf ^ 1, av);
            storeW(buf ^ 1, wv);
        }
        __syncthreads();
    }

    // ---- epilogue: combine hi+lo, spill logits, per-lane top-9 -------------
    float* lw = reinterpret_cast<float*>(sm + SM_WH(0)) + tg * 16 * LROW;
#pragma unroll
    for (int j = 0; j < 4; j++) {
        int col = eh * 32 + j * 8 + cp2;
        lw[n4 * LROW + col]           = dh[j][0] + dl[j][0] * INV_LOSCALE;
        lw[n4 * LROW + col + 1]       = dh[j][1] + dl[j][1] * INV_LOSCALE;
        lw[(n4 + 8) * LROW + col]     = dh[j][2] + dl[j][2] * INV_LOSCALE;
        lw[(n4 + 8) * LROW + col + 1] = dh[j][3] + dl[j][3] * INV_LOSCALE;
    }
    __syncthreads();

    if (eh == 0 && lane < 16) {
        const int tok = wtok + lane;
        const float* row = lw + lane * LROW;
        const float NEG = -3.0e38f;

        float val[9]; int idx[9];
#pragma unroll
        for (int j = 0; j < 9; j++) { val[j] = NEG; idx[j] = 0; }

#pragma unroll
        for (int e = 0; e < N_EXP; e++) {
            float cv = row[e] * SCALE + bias_sm[e];
            int   ci = e;
#pragma unroll
            for (int j = 0; j < 9; j++) {
                if (cv > val[j]) {
                    float tv = val[j]; val[j] = cv; cv = tv;
                    int   ti = idx[j]; idx[j] = ci; ci = ti;
                }
            }
        }

        float ming = val[0] - val[1];
#pragma unroll
        for (int j = 1; j < 8; j++) ming = fminf(ming, val[j] - val[j + 1]);

        float orig[TOP_K];
#pragma unroll
        for (int j = 0; j < TOP_K; j++) orig[j] = val[j] - bias_sm[idx[j]];
        float m = orig[0];
#pragma unroll
        for (int j = 1; j < TOP_K; j++) m = fmaxf(m, orig[j]);
        float ex[TOP_K], ssum = 0.0f;
#pragma unroll
        for (int j = 0; j < TOP_K; j++) { ex[j] = __expf(orig[j] - m); ssum += ex[j]; }
        float inv = 1.0f / ssum;

        float* wout = out + (size_t)tok * TOP_K;
        float* iout = out + (size_t)T * TOP_K + (size_t)tok * TOP_K;
#pragma unroll
        for (int j = 0; j < TOP_K; j++) { wout[j] = ex[j] * inv; iout[j] = (float)idx[j]; }

        if (ming < EPS) {
            int p = atomicAdd(&g_flag_count, 1);
            if (p < MAX_T) g_flags[p] = tok;
        }
    }
}

// ---------------------------------------------------------------------------
// Fixup stage 1 (panel-parallel, proven): block = (batch of 32 tokens,
// panel of 512 k). Exact serial FFMA chain ascending k within panel.
// ---------------------------------------------------------------------------
#define FB 32
#define XPITCH 34
__global__ void __launch_bounds__(256) fixup_panel_kernel(
    const float* __restrict__ x, const float* __restrict__ W)
{
    __shared__ __align__(16) float Wp[64][68];
    __shared__ __align__(16) float Xt[64][XPITCH];

    const int t = threadIdx.x;

    int F = g_flag_count;
    if (F > MAX_T) F = MAX_T;
    const int nb = (F + FB - 1) / FB;

    const int e0 = (t & 15) * 4;
    const int tq = t >> 4;
    const int sx_tok = t >> 3;
    const int sx_k0  = (t & 7) * 8;

    for (int it = blockIdx.x; it < nb * 4; it += gridDim.x) {
        const int b = it >> 2;
        const int p = it & 3;

        float accP[2][4];
#pragma unroll
        for (int i = 0; i < 2; i++)
#pragma unroll
            for (int q = 0; q < 4; q++) accP[i][q] = 0.f;

        for (int kc = p * 8; kc < p * 8 + 8; kc++) {
            __syncthreads();
            {
                int s2 = b * FB + sx_tok;
                int gt = g_flags[(s2 < F) ? s2 : (F - 1)];
                const float* xp = x + (size_t)gt * D_MODEL + kc * 64 + sx_k0;
                float4 v0 = *reinterpret_cast<const float4*>(xp);
                float4 v1 = *reinterpret_cast<const float4*>(xp + 4);
                Xt[sx_k0 + 0][sx_tok] = v0.x; Xt[sx_k0 + 1][sx_tok] = v0.y;
                Xt[sx_k0 + 2][sx_tok] = v0.z; Xt[sx_k0 + 3][sx_tok] = v0.w;
                Xt[sx_k0 + 4][sx_tok] = v1.x; Xt[sx_k0 + 5][sx_tok] = v1.y;
                Xt[sx_k0 + 6][sx_tok] = v1.z; Xt[sx_k0 + 7][sx_tok] = v1.w;
            }
#pragma unroll
            for (int j = 0; j < 4; j++) {
                int idx = t + 256 * j;
                int xe  = idx >> 4;
                int kq  = (idx & 15) * 4;
                float4 w = *reinterpret_cast<const float4*>(
                    W + (size_t)xe * D_MODEL + kc * 64 + kq);
                Wp[kq + 0][xe] = w.x;
                Wp[kq + 1][xe] = w.y;
                Wp[kq + 2][xe] = w.z;
                Wp[kq + 3][xe] = w.w;
            }
            __syncthreads();
#pragma unroll 4
            for (int k = 0; k < 64; k++) {
                float4 wvv = *reinterpret_cast<const float4*>(&Wp[k][e0]);
                float2 xvv = *reinterpret_cast<const float2*>(&Xt[k][tq * 2]);
                accP[0][0] = __fmaf_rn(xvv.x, wvv.x, accP[0][0]);
                accP[0][1] = __fmaf_rn(xvv.x, wvv.y, accP[0][1]);
                accP[0][2] = __fmaf_rn(xvv.x, wvv.z, accP[0][2]);
                accP[0][3] = __fmaf_rn(xvv.x, wvv.w, accP[0][3]);
                accP[1][0] = __fmaf_rn(xvv.y, wvv.x, accP[1][0]);
                accP[1][1] = __fmaf_rn(xvv.y, wvv.y, accP[1][1]);
                accP[1][2] = __fmaf_rn(xvv.y, wvv.z, accP[1][2]);
                accP[1][3] = __fmaf_rn(xvv.y, wvv.w, accP[1][3]);
            }
        }
#pragma unroll
        for (int i = 0; i < 2; i++) {
            float4 v = make_float4(accP[i][0], accP[i][1], accP[i][2], accP[i][3]);
            *reinterpret_cast<float4*>(
                &g_partial[(((size_t)b * FB + tq * 2 + i) * 4 + p) * 64 + e0]) = v;
        }
        __syncthreads();
    }
}

// ---------------------------------------------------------------------------
// Fixup stage 2 (combine, proven): sum 4 panel partials ascending
// (__fadd_rn), x SCALE, exact top-k, softmax, write. Ticket resets counter.
// ---------------------------------------------------------------------------
__global__ void __launch_bounds__(256) fixup_combine_kernel(
    const float* __restrict__ bias, float* __restrict__ out, int T)
{
    __shared__ float Lg[FB][66];
    __shared__ float bias_f[N_EXP];

    const int t = threadIdx.x;
    if (t < N_EXP) bias_f[t] = bias[t];

    int F = g_flag_count;
    if (F > MAX_T) F = MAX_T;
    const int nb = (F + FB - 1) / FB;

    const int tok_s = t >> 3;
    const int eg    = (t & 7) * 8;

    for (int b = blockIdx.x; b < nb; b += gridDim.x) {
        __syncthreads();
#pragma unroll
        for (int u = 0; u < 2; u++) {
            int e = eg + u * 4;
            const float* gp =
                &g_partial[(((size_t)b * FB + tok_s) * 4 + 0) * 64 + e];
            float4 p0 = *reinterpret_cast<const float4*>(gp);
            float4 p1 = *reinterpret_cast<const float4*>(gp + 64);
            float4 p2 = *reinterpret_cast<const float4*>(gp + 128);
            float4 p3 = *reinterpret_cast<const float4*>(gp + 192);
            Lg[tok_s][e + 0] = __fmul_rn(__fadd_rn(__fadd_rn(__fadd_rn(p0.x, p1.x), p2.x), p3.x), SCALE);
            Lg[tok_s][e + 1] = __fmul_rn(__fadd_rn(__fadd_rn(__fadd_rn(p0.y, p1.y), p2.y), p3.y), SCALE);
            Lg[tok_s][e + 2] = __fmul_rn(__fadd_rn(__fadd_rn(__fadd_rn(p0.z, p1.z), p2.z), p3.z), SCALE);
            Lg[tok_s][e + 3] = __fmul_rn(__fadd_rn(__fadd_rn(__fadd_rn(p0.w, p1.w), p2.w), p3.w), SCALE);
        }
        __syncthreads();

        if (t < FB && b * FB + t < F) {
            const int tok = g_flags[b * FB + t];
            const float* row = &Lg[t][0];
            unsigned long long used = 0ull;
            int sel[TOP_K]; float sl[TOP_K];
            for (int k = 0; k < TOP_K; k++) {
                float best = -3.0e38f; int bi = 0;
                for (int e = 0; e < N_EXP; e++) {
                    if ((used >> e) & 1ull) continue;
                    float bv = __fadd_rn(row[e], bias_f[e]);
                    if (bv > best) { best = bv; bi = e; }
                }
                sel[k] = bi; sl[k] = row[bi];
                used |= (1ull << bi);
            }
            float m = sl[0];
            for (int k = 1; k < TOP_K; k++) m = fmaxf(m, sl[k]);
            float ex[TOP_K], s = 0.0f;
            for (int k = 0; k < TOP_K; k++) { ex[k] = __expf(sl[k] - m); s += ex[k]; }
            float inv = 1.0f / s;
            for (int k = 0; k < TOP_K; k++) {
                out[(size_t)tok * TOP_K + k] = ex[k] * inv;
                out[(size_t)T * TOP_K + (size_t)tok * TOP_K + k] = (float)sel[k];
            }
        }
    }

    __syncthreads();
    if (t == 0) {
        __threadfence();
        int ticket = atomicAdd(&g_done_count, 1);
        if (ticket == (int)gridDim.x - 1) {
            g_flag_count = 0;
            g_done_count = 0;
            __threadfence();
        }
    }
}

// ---------------------------------------------------------------------------
extern "C" void kernel_launch(void* const* d_in, const int* in_sizes, int n_in,
                              void* d_out, int out_size)
{
    const float* x    = (const float*)d_in[0];
    const float* W    = (const float*)d_in[1];
    const float* bias = (const float*)d_in[2];
    float* out        = (float*)d_out;

    int T = in_sizes[0] / D_MODEL;  // 16384

    cudaFuncSetAttribute(router_mma_kernel,
                         cudaFuncAttributeMaxDynamicSharedMemorySize, SM_TOT);
    router_mma_kernel<<<T / CTA_TOK, 256, SM_TOT>>>(x, W, bias, out, T);
    fixup_panel_kernel<<<592, 256>>>(x, W);
    fixup_combine_kernel<<<128, 256>>>(bias, out, T);
}